// round 1
// baseline (speedup 1.0000x reference)
#include <cuda_runtime.h>
#include <math.h>

// Problem constants
#define BB 32
#define NN 1024
#define DD 512
#define HH 8

// Scratch (device globals; no allocation allowed)
__device__ float g_kh[(size_t)BB * HH * NN * DD];       // [B,H,N,D]  512 MB
__device__ float g_vh[(size_t)BB * HH * NN * DD];       // [B,H,N,D]  512 MB
__device__ float g_qh[(size_t)BB * HH * NN * DD];       // [B,H,N,D]  512 MB
__device__ float g_s [(size_t)BB * HH * NN * NN];       // [B,H,N,N]  1 GB
__device__ float g_att[(size_t)BB * NN * HH * DD];      // [B,N,H,D]  512 MB
__device__ float g_wo[(size_t)HH * DD * DD];            // [H*D, D]   8 MB

// ---------------------------------------------------------------------------
// 128x128x8 SGEMM, 256 threads, 8x8 register tile per thread.
// TB=true : C[m,e] = sum_k A[m,k] * B[e,k]   (B is Nout x K, "NT")
// TB=false: C[m,e] = sum_k A[m,k] * B[k,e]   (B is K x Nout, "NN")
// Batched over blockIdx.z with flexible stride composition:
//   A += (z/aDiv)*sA ; B += (z%bMod)*sB ; C += (z/cDiv)*sC1 + (z%cMod)*sC2
//   bias (if BIAS) indexed bias[(z%biasMod)*Nout + e]
// All dims must be multiples of 128 (M,N) and 8 (K). No bounds checks.
// ---------------------------------------------------------------------------
template<bool TB, bool BIAS>
__global__ __launch_bounds__(256, 2)
void sgemm_k(const float* __restrict__ A, const float* __restrict__ B,
             const float* __restrict__ bias, float* __restrict__ C,
             int K, int lda, int ldb, int ldc,
             int aDiv, long long sA, int bMod, long long sB,
             int cDiv, long long sC1, int cMod, long long sC2,
             int biasMod, float alpha)
{
    __shared__ float As[8][132];
    __shared__ float Bs[8][132];

    const int z = blockIdx.z;
    A += (long long)(z / aDiv) * sA;
    B += (long long)(z % bMod) * sB;
    C += (long long)(z / cDiv) * sC1 + (long long)(z % cMod) * sC2;

    const int Nout = gridDim.x * 128;
    const int tid = threadIdx.x;
    const int m0 = blockIdx.y * 128;
    const int e0 = blockIdx.x * 128;

    const int tx = tid & 15;       // 0..15 -> output cols
    const int ty = tid >> 4;       // 0..15 -> output rows

    float acc[8][8];
#pragma unroll
    for (int i = 0; i < 8; i++)
#pragma unroll
        for (int j = 0; j < 8; j++) acc[i][j] = 0.0f;

    // A-tile loader (also used for B when TB): 128 rows x 8 k-cols, float4
    const int arow = tid >> 1;          // 0..127
    const int acol = (tid & 1) * 4;     // 0 or 4

    for (int k0 = 0; k0 < K; k0 += 8) {
        // Load A tile (transposed into smem: As[k][m])
        float4 av = *(const float4*)(A + (long long)(m0 + arow) * lda + (k0 + acol));
        As[acol + 0][arow] = av.x;
        As[acol + 1][arow] = av.y;
        As[acol + 2][arow] = av.z;
        As[acol + 3][arow] = av.w;

        if (TB) {
            // B is Nout x K row-major; Bs[k][e] = B[e0+erow, k0+kc]
            float4 bv = *(const float4*)(B + (long long)(e0 + arow) * ldb + (k0 + acol));
            Bs[acol + 0][arow] = bv.x;
            Bs[acol + 1][arow] = bv.y;
            Bs[acol + 2][arow] = bv.z;
            Bs[acol + 3][arow] = bv.w;
        } else {
            // B is K x Nout row-major; Bs[k][e] = B[k0+brow, e0+bcol..]
            const int brow = tid >> 5;          // 0..7
            const int bcol = (tid & 31) * 4;    // 0..124
            float4 bv = *(const float4*)(B + (long long)(k0 + brow) * ldb + (e0 + bcol));
            *(float4*)&Bs[brow][bcol] = bv;
        }
        __syncthreads();

#pragma unroll
        for (int kk = 0; kk < 8; kk++) {
            float4 a0 = *(const float4*)&As[kk][ty * 4];
            float4 a1 = *(const float4*)&As[kk][64 + ty * 4];
            float4 b0 = *(const float4*)&Bs[kk][tx * 4];
            float4 b1 = *(const float4*)&Bs[kk][64 + tx * 4];
            float a[8] = {a0.x, a0.y, a0.z, a0.w, a1.x, a1.y, a1.z, a1.w};
            float b[8] = {b0.x, b0.y, b0.z, b0.w, b1.x, b1.y, b1.z, b1.w};
#pragma unroll
            for (int i = 0; i < 8; i++)
#pragma unroll
                for (int j = 0; j < 8; j++)
                    acc[i][j] += a[i] * b[j];
        }
        __syncthreads();
    }

    // Epilogue: rows {ty*4+i, 64+ty*4+i}, cols {tx*4+j, 64+tx*4+j}
    const float* bptr = BIAS ? (bias + (long long)(z % biasMod) * Nout) : nullptr;
#pragma unroll
    for (int ih = 0; ih < 2; ih++) {
#pragma unroll
        for (int i = 0; i < 4; i++) {
            const int m = m0 + ih * 64 + ty * 4 + i;
#pragma unroll
            for (int jh = 0; jh < 2; jh++) {
                const int e = e0 + jh * 64 + tx * 4;
                float4 out;
                out.x = acc[ih * 4 + i][jh * 4 + 0] * alpha;
                out.y = acc[ih * 4 + i][jh * 4 + 1] * alpha;
                out.z = acc[ih * 4 + i][jh * 4 + 2] * alpha;
                out.w = acc[ih * 4 + i][jh * 4 + 3] * alpha;
                if (BIAS) {
                    out.x += bptr[e + 0];
                    out.y += bptr[e + 1];
                    out.z += bptr[e + 2];
                    out.w += bptr[e + 3];
                }
                *(float4*)(C + (long long)m * ldc + e) = out;
            }
        }
    }
}

// ---------------------------------------------------------------------------
// Row softmax over 1024-wide rows; one warp per row, 8 warps per block.
// ---------------------------------------------------------------------------
__global__ void softmax_k(float* __restrict__ S)
{
    const long long row = (long long)blockIdx.x * 8 + (threadIdx.x >> 5);
    const int lane = threadIdx.x & 31;
    float4* p = (float4*)(S + row * NN);

    float4 v[8];
    float mx = -1e30f;
#pragma unroll
    for (int i = 0; i < 8; i++) {
        v[i] = p[lane + 32 * i];
        mx = fmaxf(mx, fmaxf(fmaxf(v[i].x, v[i].y), fmaxf(v[i].z, v[i].w)));
    }
#pragma unroll
    for (int o = 16; o > 0; o >>= 1) mx = fmaxf(mx, __shfl_xor_sync(0xffffffffu, mx, o));

    float sum = 0.0f;
#pragma unroll
    for (int i = 0; i < 8; i++) {
        v[i].x = __expf(v[i].x - mx);
        v[i].y = __expf(v[i].y - mx);
        v[i].z = __expf(v[i].z - mx);
        v[i].w = __expf(v[i].w - mx);
        sum += v[i].x + v[i].y + v[i].z + v[i].w;
    }
#pragma unroll
    for (int o = 16; o > 0; o >>= 1) sum += __shfl_xor_sync(0xffffffffu, sum, o);
    const float inv = 1.0f / sum;

#pragma unroll
    for (int i = 0; i < 8; i++) {
        v[i].x *= inv; v[i].y *= inv; v[i].z *= inv; v[i].w *= inv;
        p[lane + 32 * i] = v[i];
    }
}

// ---------------------------------------------------------------------------
// Permute Wo[e, d*H+h] -> g_wo[(h*D+d), e]  (so out-proj is a plain NN GEMM)
// ---------------------------------------------------------------------------
__global__ void permwo_k(const float* __restrict__ Wo, float* __restrict__ W2)
{
    const int idx = blockIdx.x * 256 + threadIdx.x;   // 0 .. H*D*D-1
    const int e  = idx & (DD - 1);
    const int kp = idx >> 9;         // h*D + d
    const int d  = kp & (DD - 1);
    const int h  = kp >> 9;
    W2[idx] = Wo[(long long)e * (HH * DD) + d * HH + h];
}

extern "C" void kernel_launch(void* const* d_in, const int* in_sizes, int n_in,
                              void* d_out, int out_size)
{
    const float* k  = (const float*)d_in[0];
    const float* v  = (const float*)d_in[1];
    const float* q  = (const float*)d_in[2];
    const float* Wk = (const float*)d_in[3];
    const float* bk = (const float*)d_in[4];
    const float* Wv = (const float*)d_in[5];
    const float* bv = (const float*)d_in[6];
    const float* Wq = (const float*)d_in[7];
    const float* bq = (const float*)d_in[8];
    const float* Wo = (const float*)d_in[9];
    const float* bo = (const float*)d_in[10];
    float* out = (float*)d_out;

    float *kh, *vh, *qh, *s, *att, *w2;
    cudaGetSymbolAddress((void**)&kh,  g_kh);
    cudaGetSymbolAddress((void**)&vh,  g_vh);
    cudaGetSymbolAddress((void**)&qh,  g_qh);
    cudaGetSymbolAddress((void**)&s,   g_s);
    cudaGetSymbolAddress((void**)&att, g_att);
    cudaGetSymbolAddress((void**)&w2,  g_wo);

    const long long ND  = (long long)NN * DD;       // 524288
    const long long DDd = (long long)DD * DD;       // 262144
    const long long NNs = (long long)NN * NN;       // 1048576
    const float alpha_s = 1.0f / sqrtf((float)DD);

    dim3 blk(256);

    // --- Per-head projections: kh/vh/qh[b,h,n,e] = X[b,n,:].W[h,e,:] + b[h,e]
    // grid: (Nout/128=4, M/128=8, B*H=256)
    sgemm_k<true, true><<<dim3(4, 8, BB * HH), blk>>>(
        k, Wk, bk, kh, DD, DD, DD, DD,
        HH, ND, HH, DDd, 1, ND, 1, 0, HH, 1.0f);
    sgemm_k<true, true><<<dim3(4, 8, BB * HH), blk>>>(
        v, Wv, bv, vh, DD, DD, DD, DD,
        HH, ND, HH, DDd, 1, ND, 1, 0, HH, 1.0f);
    sgemm_k<true, true><<<dim3(4, 8, BB * HH), blk>>>(
        q, Wq, bq, qh, DD, DD, DD, DD,
        HH, ND, HH, DDd, 1, ND, 1, 0, HH, 1.0f);

    // --- Scores: s[b,h,i,j] = (qh[i,:].kh[j,:]) / sqrt(D)
    sgemm_k<true, false><<<dim3(8, 8, BB * HH), blk>>>(
        qh, kh, nullptr, s, DD, DD, DD, NN,
        1, ND, BB * HH, ND, 1, NNs, 1, 0, 1, alpha_s);

    // --- Softmax over last axis (rows of s)
    softmax_k<<<BB * HH * NN / 8, blk>>>(s);

    // --- AV: att[b,n,h,d] = sum_j w[i=n,j] vh[b,h,j,d]   (store [B,N,H,D])
    sgemm_k<false, false><<<dim3(4, 8, BB * HH), blk>>>(
        s, vh, nullptr, att, NN, NN, DD, HH * DD,
        1, NNs, BB * HH, ND, HH, (long long)NN * HH * DD, HH, DD, 1, 1.0f);

    // --- Permute Wo into [h*D+d, e] layout
    permwo_k<<<(HH * DD * DD) / 256, blk>>>(Wo, w2);

    // --- Output projection: out[m,e] = att_flat[m, :] . w2[:, e] + bo[e]
    sgemm_k<false, true><<<dim3(4, 256, 1), blk>>>(
        att, w2, bo, out, HH * DD, HH * DD, DD, DD,
        1, 0, 1, 0, 1, 0, 1, 0, 1, 1.0f);
}

// round 4
// speedup vs baseline: 3.1346x; 3.1346x over previous
#include <cuda_runtime.h>
#include <math.h>
#include <stdint.h>

#define BB 32
#define NN 1024
#define DD 512
#define HH 8

// ---------------- scratch (device globals; no allocation allowed) ----------
__device__ float g_kh[(size_t)BB * HH * NN * DD];   // [B,H,N,D]
__device__ float g_vh[(size_t)BB * HH * NN * DD];   // [B,H,N,D]
__device__ float g_qh[(size_t)BB * HH * NN * DD];   // [B,H,N,D]
__device__ float g_vt[(size_t)BB * HH * DD * NN];   // [B,H,D,N]
__device__ float g_s [(size_t)BB * HH * NN * NN];   // [B,H,N,N]
__device__ float g_att[(size_t)BB * NN * HH * DD];  // [B,N,H,D] (early: rounded k/v/q)
__device__ float g_wr[(size_t)3 * HH * DD * DD];    // rounded Wk,Wv,Wq
__device__ float g_wo[(size_t)HH * DD * DD];        // Wo permuted+rounded [e][h*D+d]

__device__ __forceinline__ float rna_tf32(float x) {
    float r;
    asm("cvt.rna.tf32.f32 %0, %1;" : "=f"(r) : "f"(x));
    return r;
}

// ---------------------------------------------------------------------------
// TF32 mma.sync NT GEMM: C[m,e] = alpha * sum_k A[m,k]*B[e,k] (+bias) (+rna)
// 128x128 tile, K-chunk 32, 2-stage cp.async double buffer, 256 threads.
// Warp grid 2x4 -> warp tile 64x32 -> 4x4 m16n8k8 MMAs per k8 step.
// Batched over blockIdx.z:
//   A += (z/aDiv)*sA ; B += (z%bMod)*sB ; C += (z/cDiv)*sC1 + (z%cMod)*sC2
// Requires: M,Nout multiples of 128; K multiple of 32.
// ---------------------------------------------------------------------------
#define TPITCH 36                       // floats per smem row (pad 32->36, 144B, 16B-aligned)
#define TILEF  (128 * TPITCH)           // 4608 floats per tile
#define SMEMF  (4 * TILEF)              // A0,A1,B0,B1
#define SMEMB  (SMEMF * 4)              // 73728 bytes

__device__ __forceinline__ void ldg_tile(float* dst, const float* __restrict__ src,
                                         int ld, int row0, int k0, int tid) {
#pragma unroll
    for (int i = 0; i < 4; ++i) {
        int idx = tid + 256 * i;              // 0..1023
        int r = idx >> 3;                     // 0..127
        int c = idx & 7;                      // 0..7 (16B chunks)
        uint32_t sa = (uint32_t)__cvta_generic_to_shared(dst + r * TPITCH + c * 4);
        const float* g = src + (long long)(row0 + r) * ld + k0 + c * 4;
        asm volatile("cp.async.cg.shared.global [%0], [%1], 16;" :: "r"(sa), "l"(g));
    }
}

template<bool BIAS>
__global__ __launch_bounds__(256, 2)
void mma_gemm(const float* __restrict__ A, const float* __restrict__ B,
              const float* __restrict__ bias, float* __restrict__ C,
              int K, int lda, int ldb, int ldc,
              int aDiv, long long sA, int bMod, long long sB,
              int cDiv, long long sC1, int cMod, long long sC2,
              int biasMod, float alpha, int rnd)
{
    extern __shared__ float sm[];
    float* As = sm;                 // [2][TILEF]
    float* Bs = sm + 2 * TILEF;     // [2][TILEF]

    const int z = blockIdx.z;
    A += (long long)(z / aDiv) * sA;
    B += (long long)(z % bMod) * sB;
    C += (long long)(z / cDiv) * sC1 + (long long)(z % cMod) * sC2;

    const int Nout = gridDim.x * 128;
    const int tid  = threadIdx.x;
    const int lane = tid & 31;
    const int wid  = tid >> 5;
    const int wm   = (wid & 1) * 64;      // warp row offset in tile
    const int wn   = (wid >> 1) * 32;     // warp col offset in tile
    const int m0   = blockIdx.y * 128;
    const int e0   = blockIdx.x * 128;
    const int gid  = lane >> 2;           // 0..7
    const int tg   = lane & 3;            // 0..3

    float acc[4][4][4];
#pragma unroll
    for (int i = 0; i < 4; i++)
#pragma unroll
        for (int j = 0; j < 4; j++)
#pragma unroll
            for (int t = 0; t < 4; t++) acc[i][j][t] = 0.0f;

    // prologue: chunk 0 -> stage 0
    ldg_tile(As, A, lda, m0, 0, tid);
    ldg_tile(Bs, B, ldb, e0, 0, tid);
    asm volatile("cp.async.commit_group;" ::: "memory");

    const int NC = K >> 5;
    for (int c = 0; c < NC; ++c) {
        const int s = c & 1;
        asm volatile("cp.async.wait_group 0;" ::: "memory");
        __syncthreads();

        if (c + 1 < NC) {
            const int s2 = (c + 1) & 1;
            ldg_tile(As + s2 * TILEF, A, lda, m0, (c + 1) * 32, tid);
            ldg_tile(Bs + s2 * TILEF, B, ldb, e0, (c + 1) * 32, tid);
            asm volatile("cp.async.commit_group;" ::: "memory");
        }

        const float* as = As + s * TILEF;
        const float* bs = Bs + s * TILEF;

#pragma unroll
        for (int ks = 0; ks < 4; ++ks) {
            const int kk = ks * 8;
            uint32_t af[4][4];
            uint32_t bf[4][2];
#pragma unroll
            for (int i = 0; i < 4; ++i) {
                const float* ap = as + (wm + i * 16 + gid) * TPITCH + kk + tg;
                af[i][0] = __float_as_uint(ap[0]);
                af[i][1] = __float_as_uint(ap[8 * TPITCH]);
                af[i][2] = __float_as_uint(ap[4]);
                af[i][3] = __float_as_uint(ap[8 * TPITCH + 4]);
            }
#pragma unroll
            for (int j = 0; j < 4; ++j) {
                const float* bp = bs + (wn + j * 8 + gid) * TPITCH + kk + tg;
                bf[j][0] = __float_as_uint(bp[0]);
                bf[j][1] = __float_as_uint(bp[4]);
            }
#pragma unroll
            for (int i = 0; i < 4; ++i)
#pragma unroll
                for (int j = 0; j < 4; ++j)
                    asm volatile(
                        "mma.sync.aligned.m16n8k8.row.col.f32.tf32.tf32.f32 "
                        "{%0,%1,%2,%3}, {%4,%5,%6,%7}, {%8,%9}, {%0,%1,%2,%3};"
                        : "+f"(acc[i][j][0]), "+f"(acc[i][j][1]),
                          "+f"(acc[i][j][2]), "+f"(acc[i][j][3])
                        : "r"(af[i][0]), "r"(af[i][1]), "r"(af[i][2]), "r"(af[i][3]),
                          "r"(bf[j][0]), "r"(bf[j][1]));
        }
    }

    // epilogue
    const float* bptr = BIAS ? (bias + (long long)(z % biasMod) * Nout) : nullptr;
#pragma unroll
    for (int i = 0; i < 4; ++i) {
        const int r0 = m0 + wm + i * 16 + gid;
#pragma unroll
        for (int j = 0; j < 4; ++j) {
            const int cc = e0 + wn + j * 8 + tg * 2;
#pragma unroll
            for (int hf = 0; hf < 2; ++hf) {
                const int r = r0 + hf * 8;
                float x = acc[i][j][hf * 2 + 0] * alpha;
                float y = acc[i][j][hf * 2 + 1] * alpha;
                if (BIAS) { x += bptr[cc]; y += bptr[cc + 1]; }
                if (rnd)  { x = rna_tf32(x); y = rna_tf32(y); }
                *(float2*)(C + (long long)r * ldc + cc) = make_float2(x, y);
            }
        }
    }
}

// ---------------------------------------------------------------------------
// Row softmax over 1024-wide rows (one warp per row); rounds output to tf32.
// ---------------------------------------------------------------------------
__global__ void softmax_k(float* __restrict__ S)
{
    const long long row = (long long)blockIdx.x * 8 + (threadIdx.x >> 5);
    const int lane = threadIdx.x & 31;
    float4* p = (float4*)(S + row * NN);

    float4 v[8];
    float mx = -1e30f;
#pragma unroll
    for (int i = 0; i < 8; i++) {
        v[i] = p[lane + 32 * i];
        mx = fmaxf(mx, fmaxf(fmaxf(v[i].x, v[i].y), fmaxf(v[i].z, v[i].w)));
    }
#pragma unroll
    for (int o = 16; o > 0; o >>= 1) mx = fmaxf(mx, __shfl_xor_sync(0xffffffffu, mx, o));

    float sum = 0.0f;
#pragma unroll
    for (int i = 0; i < 8; i++) {
        v[i].x = __expf(v[i].x - mx);
        v[i].y = __expf(v[i].y - mx);
        v[i].z = __expf(v[i].z - mx);
        v[i].w = __expf(v[i].w - mx);
        sum += v[i].x + v[i].y + v[i].z + v[i].w;
    }
#pragma unroll
    for (int o = 16; o > 0; o >>= 1) sum += __shfl_xor_sync(0xffffffffu, sum, o);
    const float inv = 1.0f / sum;

#pragma unroll
    for (int i = 0; i < 8; i++) {
        v[i].x = rna_tf32(v[i].x * inv);
        v[i].y = rna_tf32(v[i].y * inv);
        v[i].z = rna_tf32(v[i].z * inv);
        v[i].w = rna_tf32(v[i].w * inv);
        p[lane + 32 * i] = v[i];
    }
}

// ---------------------------------------------------------------------------
__global__ void round_k(const float* __restrict__ x, float* __restrict__ y)
{
    const long long i = ((long long)blockIdx.x * 256 + threadIdx.x) * 4;
    float4 v = *(const float4*)(x + i);
    v.x = rna_tf32(v.x); v.y = rna_tf32(v.y);
    v.z = rna_tf32(v.z); v.w = rna_tf32(v.w);
    *(float4*)(y + i) = v;
}

// Per-(b,h) transpose: vh [N,D] -> vt [D,N]
__global__ void transpose_k(const float* __restrict__ in, float* __restrict__ out)
{
    __shared__ float t[32][33];
    const long long base = (long long)blockIdx.z * NN * DD;
    const int c0 = blockIdx.x * 32;   // D
    const int r0 = blockIdx.y * 32;   // N
    const int tx = threadIdx.x, ty = threadIdx.y;
#pragma unroll
    for (int k = 0; k < 4; k++)
        t[ty + 8 * k][tx] = in[base + (long long)(r0 + ty + 8 * k) * DD + c0 + tx];
    __syncthreads();
#pragma unroll
    for (int k = 0; k < 4; k++)
        out[base + (long long)(c0 + ty + 8 * k) * NN + r0 + tx] = t[tx][ty + 8 * k];
}

// Permute + round Wo: w2[e][h*D+d] = rna(Wo[e][d*H+h])
__global__ void permwo_k(const float* __restrict__ Wo, float* __restrict__ W2)
{
    const int idx = blockIdx.x * 256 + threadIdx.x;  // e*(H*D) + (h*D+d)
    const int e  = idx >> 12;
    const int kp = idx & 4095;
    const int h  = kp >> 9;
    const int d  = kp & 511;
    W2[idx] = rna_tf32(Wo[(long long)e * (HH * DD) + d * HH + h]);
}

// ---------------------------------------------------------------------------
extern "C" void kernel_launch(void* const* d_in, const int* in_sizes, int n_in,
                              void* d_out, int out_size)
{
    const float* k  = (const float*)d_in[0];
    const float* v  = (const float*)d_in[1];
    const float* q  = (const float*)d_in[2];
    const float* Wk = (const float*)d_in[3];
    const float* bk = (const float*)d_in[4];
    const float* Wv = (const float*)d_in[5];
    const float* bv = (const float*)d_in[6];
    const float* Wq = (const float*)d_in[7];
    const float* bq = (const float*)d_in[8];
    const float* Wo = (const float*)d_in[9];
    const float* bo = (const float*)d_in[10];
    float* out = (float*)d_out;

    float *kh, *vh, *qh, *vt, *s, *att, *wr, *w2;
    cudaGetSymbolAddress((void**)&kh,  g_kh);
    cudaGetSymbolAddress((void**)&vh,  g_vh);
    cudaGetSymbolAddress((void**)&qh,  g_qh);
    cudaGetSymbolAddress((void**)&vt,  g_vt);
    cudaGetSymbolAddress((void**)&s,   g_s);
    cudaGetSymbolAddress((void**)&att, g_att);
    cudaGetSymbolAddress((void**)&wr,  g_wr);
    cudaGetSymbolAddress((void**)&w2,  g_wo);

    cudaFuncSetAttribute(mma_gemm<true>,  cudaFuncAttributeMaxDynamicSharedMemorySize, SMEMB);
    cudaFuncSetAttribute(mma_gemm<false>, cudaFuncAttributeMaxDynamicSharedMemorySize, SMEMB);

    const long long ND  = (long long)NN * DD;
    const long long WD  = (long long)DD * DD;
    const long long NNs = (long long)NN * NN;
    const float alpha_s = 1.0f / sqrtf((float)DD);

    float* rk = att;
    float* rv = att + (long long)BB * NN * DD;
    float* rq = att + 2LL * BB * NN * DD;
    float* w0 = wr;
    float* w1 = wr + HH * WD;
    float* w2r = wr + 2LL * HH * WD;

    dim3 blk256(256);

    // 1) round inputs + weights to tf32 (RNA)
    round_k<<<(BB * NN * DD) / 1024, blk256>>>(k, rk);
    round_k<<<(BB * NN * DD) / 1024, blk256>>>(v, rv);
    round_k<<<(BB * NN * DD) / 1024, blk256>>>(q, rq);
    round_k<<<(HH * WD) / 1024, blk256>>>(Wk, w0);
    round_k<<<(HH * WD) / 1024, blk256>>>(Wv, w1);
    round_k<<<(HH * WD) / 1024, blk256>>>(Wq, w2r);

    // 2) projections (epilogue rounds)
    mma_gemm<true><<<dim3(4, 8, BB * HH), blk256, SMEMB>>>(
        rk, w0, bk, kh, DD, DD, DD, DD,
        HH, ND, HH, WD, 1, ND, 1, 0, HH, 1.0f, 1);
    mma_gemm<true><<<dim3(4, 8, BB * HH), blk256, SMEMB>>>(
        rv, w1, bv, vh, DD, DD, DD, DD,
        HH, ND, HH, WD, 1, ND, 1, 0, HH, 1.0f, 1);
    mma_gemm<true><<<dim3(4, 8, BB * HH), blk256, SMEMB>>>(
        rq, w2r, bq, qh, DD, DD, DD, DD,
        HH, ND, HH, WD, 1, ND, 1, 0, HH, 1.0f, 1);

    // 3) scores: s = qh . kh^T / sqrt(D)
    mma_gemm<false><<<dim3(8, 8, BB * HH), blk256, SMEMB>>>(
        qh, kh, nullptr, s, DD, DD, DD, NN,
        1, ND, BB * HH, ND, 1, NNs, 1, 0, 1, alpha_s, 0);

    // 4) softmax (rounds to tf32)
    softmax_k<<<BB * HH * NN / 8, blk256>>>(s);

    // 5) transpose vh -> vt
    transpose_k<<<dim3(DD / 32, NN / 32, BB * HH), dim3(32, 8)>>>(vh, vt);

    // 6) AV: att[b,n,h,d] (rounds; overwrites rounded inputs)
    mma_gemm<false><<<dim3(4, 8, BB * HH), blk256, SMEMB>>>(
        s, vt, nullptr, att, NN, NN, NN, HH * DD,
        1, NNs, BB * HH, ND, HH, (long long)NN * HH * DD, HH, DD, 1, 1.0f, 1);

    // 7) permute + round Wo
    permwo_k<<<(HH * DD * DD) / 256, blk256>>>(Wo, w2);

    // 8) output projection (final, no rounding)
    mma_gemm<true><<<dim3(4, 256, 1), blk256, SMEMB>>>(
        att, w2, bo, out, HH * DD, HH * DD, HH * DD, DD,
        1, 0, 1, 0, 1, 0, 1, 0, 1, 1.0f, 0);
}